// round 7
// baseline (speedup 1.0000x reference)
#include <cuda_runtime.h>
#include <cstdint>

// ---------------- problem constants ----------------
#define NCTA 148
#define NTHR 256
#define B    64
#define H    512
#define H3   1536
#define V    32000
#define S    64
#define AP   514        // activation smem pitch (float2-aligned, broadcast reads)
#define GWP  513        // gates W smem pitch (odd -> conflict-free LDS.32)
#define GJT  32         // gates j-tile per CTA (48 CTAs per matrix)
#define FVT  224        // FC vocab tile per CTA (143 CTAs cover 32000)
#define FKC  32         // FC k-chunk staged in smem
#define FWP  33         // FC W smem pitch (odd -> conflict-free LDS.32)

// smem: max(gates: 64*514 + 32*513 + 64tok , fc: 64*514 + 224*33)
#define SMEM_FLOATS (B*AP + GJT*GWP + 64)
#define SMEM_BYTES  (SMEM_FLOATS * 4)

// ---------------- persistent device state ----------------
__device__ float g_h [B*H];
__device__ float g_gi[B*H3];
__device__ float g_gh[B*H3];
__device__ unsigned long long g_key[B];
__device__ unsigned g_count;

// ---------------- helpers ----------------
union F2U { float2 f; unsigned long long u; };

static __device__ __forceinline__ float2 ffma2(float2 a, float2 b, float2 c) {
    F2U A, Bv, C, D;
    A.f = a; Bv.f = b; C.f = c;
    asm("fma.rn.f32x2 %0, %1, %2, %3;" : "=l"(D.u) : "l"(A.u), "l"(Bv.u), "l"(C.u));
    return D.f;
}

static __device__ __forceinline__ void gsync(unsigned target) {
    __syncthreads();
    if (threadIdx.x == 0) {
        __threadfence();
        atomicAdd(&g_count, 1u);
        while (*(volatile unsigned*)&g_count < target) { __nanosleep(64); }
        __threadfence();
    }
    __syncthreads();
}

// sortable key: larger pred -> larger key; ties -> smaller v wins (jnp.argmax first-hit)
static __device__ __forceinline__ unsigned long long makeKey(float p, int v) {
    unsigned u = __float_as_uint(p);
    u = (u & 0x80000000u) ? ~u : (u | 0x80000000u);
    return ((unsigned long long)u << 32) | (unsigned long long)(0xFFFFFFFFu - (unsigned)v);
}

// ---------------- gates: gi = x@Wih^T + bih (CTA 0..47), gh = h@Whh^T + bhh (CTA 48..95) ----------------
static __device__ void gates_pass(int cta, int tid,
                                  const float* __restrict__ Wih, const float* __restrict__ Whh,
                                  const float* __restrict__ bih, const float* __restrict__ bhh,
                                  const float* __restrict__ emb, const int* __restrict__ src,
                                  int t, bool enc)
{
    extern __shared__ float sm[];
    float* a_s  = sm;                    // [64][AP]
    float* w_s  = sm + B*AP;             // [GJT][GWP]
    int*   tok_s = (int*)(w_s + GJT*GWP);

    if (cta >= 96) return;
    const bool isGi = (cta < 48);
    const int  j0   = (isGi ? cta : cta - 48) * GJT;
    const float* Wm   = isGi ? Wih : Whh;
    const float* bias = isGi ? bih : bhh;

    if (isGi) {
        if (tid < B) {
            int tok;
            if (enc)          tok = src[tid*S + t];
            else if (t == 0)  tok = 0;  // SOS
            else {
                unsigned long long k = __ldcg(&g_key[tid]);
                tok = (int)(0xFFFFFFFFu - (unsigned)(k & 0xFFFFFFFFull));
            }
            tok_s[tid] = tok;
        }
        __syncthreads();
        for (int idx = tid; idx < B*(H/4); idx += NTHR) {
            int b = idx >> 7, q = idx & 127;
            float4 v4 = *(const float4*)(emb + (size_t)tok_s[b]*H + 4*q);
            float* d = a_s + b*AP + 4*q;
            d[0]=v4.x; d[1]=v4.y; d[2]=v4.z; d[3]=v4.w;
        }
    } else {
        for (int idx = tid; idx < B*(H/4); idx += NTHR) {
            int b = idx >> 7, q = idx & 127;
            float4 v4 = __ldcg((const float4*)(g_h + b*H + 4*q));
            float* d = a_s + b*AP + 4*q;
            d[0]=v4.x; d[1]=v4.y; d[2]=v4.z; d[3]=v4.w;
        }
    }
    for (int idx = tid; idx < GJT*(H/4); idx += NTHR) {
        int r = idx >> 7, q = idx & 127;
        float4 v4 = *(const float4*)(Wm + (size_t)(j0 + r)*H + 4*q);
        float* d = w_s + r*GWP + 4*q;
        d[0]=v4.x; d[1]=v4.y; d[2]=v4.z; d[3]=v4.w;
    }
    __syncthreads();

    const int tx = tid & 31, ty = tid >> 5;
    float2 acc[8];
    #pragma unroll
    for (int i = 0; i < 8; i++) acc[i] = make_float2(0.f, 0.f);

    const float* wr = w_s + tx*GWP;
    const float* ab = a_s + (ty*8)*AP;
    #pragma unroll 4
    for (int kp = 0; kp < H/2; kp++) {
        float2 w2 = make_float2(wr[2*kp], wr[2*kp + 1]);
        #pragma unroll
        for (int i = 0; i < 8; i++) {
            float2 a2 = *(const float2*)(ab + i*AP + 2*kp);
            acc[i] = ffma2(a2, w2, acc[i]);
        }
    }
    const int j = j0 + tx;
    const float bv = bias[j];
    float* dst = isGi ? g_gi : g_gh;
    #pragma unroll
    for (int i = 0; i < 8; i++)
        __stcg(dst + (size_t)(ty*8 + i)*H3 + j, acc[i].x + acc[i].y + bv);
}

// ---------------- GRU combine + key reset ----------------
static __device__ void combine_pass(int cta, int tid)
{
    int g = cta*NTHR + tid;
    if (g < B) __stcg(&g_key[g], 0ull);
    if (g < B*H) {
        int b = g >> 9, i = g & (H-1);
        const float* gi = g_gi + (size_t)b*H3;
        const float* gh = g_gh + (size_t)b*H3;
        float ir = __ldcg(gi + i),       hr = __ldcg(gh + i);
        float iz = __ldcg(gi + H + i),   hz = __ldcg(gh + H + i);
        float in_= __ldcg(gi + 2*H + i), hn = __ldcg(gh + 2*H + i);
        float r = 1.f / (1.f + expf(-(ir + hr)));
        float z = 1.f / (1.f + expf(-(iz + hz)));
        float n = tanhf(in_ + r*hn);
        float h = __ldcg(g_h + g);
        __stcg(g_h + g, (1.f - z)*n + z*h);
    }
}

// ---------------- FC + argmax: pred = h@fcW^T + fcb ----------------
static __device__ void fc_pass(int cta, int tid,
                               const float* __restrict__ fcW, const float* __restrict__ fcb,
                               float* __restrict__ out, int t, int T)
{
    extern __shared__ float sm[];
    float* h_s = sm;              // [64][AP]
    float* w_s = sm + B*AP;       // [FVT][FWP]
    const int v0 = cta * FVT;
    if (v0 >= V) return;

    for (int idx = tid; idx < B*(H/4); idx += NTHR) {
        int b = idx >> 7, q = idx & 127;
        float4 v4 = __ldcg((const float4*)(g_h + b*H + 4*q));
        float* d = h_s + b*AP + 4*q;
        d[0]=v4.x; d[1]=v4.y; d[2]=v4.z; d[3]=v4.w;
    }

    const int tx = tid & 31, ty = tid >> 5;
    float2 acc[7][8];
    #pragma unroll
    for (int i = 0; i < 7; i++)
        #pragma unroll
        for (int j = 0; j < 8; j++) acc[i][j] = make_float2(0.f, 0.f);

    for (int kc = 0; kc < H/FKC; kc++) {
        const int k0 = kc * FKC;
        __syncthreads();  // also covers initial h_s staging on kc==0
        for (int idx = tid; idx < FVT*(FKC/4); idx += NTHR) {
            int r = idx >> 3, q = idx & 7;
            int v = v0 + r; if (v >= V) v = v0;
            float4 w4 = *(const float4*)(fcW + (size_t)v*H + k0 + 4*q);
            float* d = w_s + r*FWP + 4*q;
            d[0]=w4.x; d[1]=w4.y; d[2]=w4.z; d[3]=w4.w;
        }
        __syncthreads();
        #pragma unroll 2
        for (int kp = 0; kp < FKC/2; kp++) {
            float2 h2[8];
            #pragma unroll
            for (int j = 0; j < 8; j++)
                h2[j] = *(const float2*)(h_s + (ty*8 + j)*AP + k0 + 2*kp);
            #pragma unroll
            for (int i = 0; i < 7; i++) {
                const float* wp = w_s + (tx + 32*i)*FWP + 2*kp;
                float2 w2 = make_float2(wp[0], wp[1]);
                #pragma unroll
                for (int j = 0; j < 8; j++)
                    acc[i][j] = ffma2(h2[j], w2, acc[i][j]);
            }
        }
    }

    unsigned long long bestKey[8];
    #pragma unroll
    for (int j = 0; j < 8; j++) bestKey[j] = 0ull;

    #pragma unroll
    for (int i = 0; i < 7; i++) {
        int v = v0 + tx + 32*i;
        if (v < V) {
            float bv = fcb[v];
            #pragma unroll
            for (int j = 0; j < 8; j++) {
                float p = acc[i][j].x + acc[i][j].y + bv;
                int b = ty*8 + j;
                out[((size_t)b*T + t)*V + v] = p;
                unsigned long long key = makeKey(p, v);
                if (key > bestKey[j]) bestKey[j] = key;
            }
        }
    }
    #pragma unroll
    for (int j = 0; j < 8; j++) {
        unsigned long long k = bestKey[j];
        #pragma unroll
        for (int off = 16; off > 0; off >>= 1) {
            unsigned long long o = __shfl_down_sync(0xFFFFFFFFu, k, off);
            if (o > k) k = o;
        }
        if (tx == 0) atomicMax(&g_key[ty*8 + j], k);
    }
}

// ---------------- kernels ----------------
__global__ void init_kernel()
{
    int g = blockIdx.x * blockDim.x + threadIdx.x;
    if (g < B*H) g_h[g] = 0.f;
    if (g < B)   g_key[g] = 0ull;
    if (g == 0)  g_count = 0u;
}

__global__ void __launch_bounds__(NTHR, 1) seq2seq_kernel(
    const int* __restrict__ src, const float* __restrict__ emb,
    const float* __restrict__ eWih, const float* __restrict__ eWhh,
    const float* __restrict__ ebih, const float* __restrict__ ebhh,
    const float* __restrict__ dWih, const float* __restrict__ dWhh,
    const float* __restrict__ dbih, const float* __restrict__ dbhh,
    const float* __restrict__ fcW,  const float* __restrict__ fcb,
    float* __restrict__ out, int T)
{
    const int cta = blockIdx.x, tid = threadIdx.x;
    unsigned gen = 0;

    // ---- encoder ----
    for (int t = 0; t < S; t++) {
        gates_pass(cta, tid, eWih, eWhh, ebih, ebhh, emb, src, t, true);
        gsync(++gen * NCTA);
        combine_pass(cta, tid);
        gsync(++gen * NCTA);
    }
    // ---- decoder ----
    for (int t = 0; t < T; t++) {
        gates_pass(cta, tid, dWih, dWhh, dbih, dbhh, emb, src, t, false);
        gsync(++gen * NCTA);
        combine_pass(cta, tid);
        gsync(++gen * NCTA);
        fc_pass(cta, tid, fcW, fcb, out, t, T);
        gsync(++gen * NCTA);
    }
}

extern "C" void kernel_launch(void* const* d_in, const int* in_sizes, int n_in,
                              void* d_out, int out_size)
{
    const int*   src  = (const int*)  d_in[0];
    const float* emb  = (const float*)d_in[1];
    const float* eWih = (const float*)d_in[2];
    const float* eWhh = (const float*)d_in[3];
    const float* ebih = (const float*)d_in[4];
    const float* ebhh = (const float*)d_in[5];
    const float* dWih = (const float*)d_in[6];
    const float* dWhh = (const float*)d_in[7];
    const float* dbih = (const float*)d_in[8];
    const float* dbhh = (const float*)d_in[9];
    const float* fcW  = (const float*)d_in[10];
    const float* fcb  = (const float*)d_in[11];
    float* out = (float*)d_out;
    const int T = out_size / (B * V);   // 80

    cudaFuncSetAttribute(seq2seq_kernel,
                         cudaFuncAttributeMaxDynamicSharedMemorySize, SMEM_BYTES);

    init_kernel<<<64, 512>>>();
    seq2seq_kernel<<<NCTA, NTHR, SMEM_BYTES>>>(
        src, emb, eWih, eWhh, ebih, ebhh,
        dWih, dWhh, dbih, dbhh, fcW, fcb, out, T);
}

// round 8
// speedup vs baseline: 2.1407x; 2.1407x over previous
#include <cuda_runtime.h>
#include <cstdint>

// ---------------- problem constants ----------------
#define NCTA 148
#define NTHR 512
#define B    64
#define H    512
#define H3   1536
#define V    32000
#define S    64

#define KC    32          // k-chunk
#define PCH   36          // chunk row pitch (floats): 144B, 16B-aligned, LDS.128 conflict-free
#define FVT   224         // FC vocab rows per CTA (143 CTAs)
#define GJT   32          // gates j rows per CTA (48+48 CTAs)
#define GWP   516         // gates full-K W pitch (2064B, 16B-aligned, conflict-free)

// smem arena (floats):
//   [0 .. 4608)        : a/h chunk double buffer  2 x (64*36)
//   [4608 .. 21120)    : FC W double buffer 2 x (224*36)=16128  OR gates W (32*516)=16512
//   [21120 .. 21184)   : token ints
#define SA    0
#define SWOFF 4608
#define STOK  21120
#define SMEM_FLOATS 21184
#define SMEM_BYTES  (SMEM_FLOATS * 4)
#define ACH   (B*PCH)      // 2304
#define WCH   (FVT*PCH)    // 8064

// ---------------- persistent device state ----------------
__device__ float g_h [B*H];
__device__ float g_gi[B*H3];
__device__ float g_gh[B*H3];
__device__ unsigned long long g_key[B];
__device__ unsigned g_count;

// ---------------- helpers ----------------
union F2U { float2 f; unsigned long long u; };

static __device__ __forceinline__ float2 ffma2(float2 a, float2 b, float2 c) {
    F2U A, Bv, C, D;
    A.f = a; Bv.f = b; C.f = c;
    asm("fma.rn.f32x2 %0, %1, %2, %3;" : "=l"(D.u) : "l"(A.u), "l"(Bv.u), "l"(C.u));
    return D.f;
}

static __device__ __forceinline__ void cpasync16(float* dst, const float* src) {
    unsigned d = (unsigned)__cvta_generic_to_shared(dst);
    asm volatile("cp.async.cg.shared.global [%0], [%1], 16;" :: "r"(d), "l"(src));
}
static __device__ __forceinline__ void cp_commit() {
    asm volatile("cp.async.commit_group;");
}
template<int N> static __device__ __forceinline__ void cp_wait() {
    asm volatile("cp.async.wait_group %0;" :: "n"(N));
}

static __device__ __forceinline__ void gsync(unsigned target) {
    __syncthreads();
    if (threadIdx.x == 0) {
        __threadfence();
        atomicAdd(&g_count, 1u);
        while (*(volatile unsigned*)&g_count < target) { __nanosleep(64); }
        __threadfence();
    }
    __syncthreads();
}

// sortable key: larger pred -> larger key; ties -> smaller v wins (jnp.argmax first-hit)
static __device__ __forceinline__ unsigned long long makeKey(float p, int v) {
    unsigned u = __float_as_uint(p);
    u = (u & 0x80000000u) ? ~u : (u | 0x80000000u);
    return ((unsigned long long)u << 32) | (unsigned long long)(0xFFFFFFFFu - (unsigned)v);
}

// ---------------- gates: gi = x@Wih^T + bih (CTA 0..47), gh = h@Whh^T + bhh (CTA 48..95) ----
static __device__ void gates_pass(int cta, int tid,
                                  const float* __restrict__ Wih, const float* __restrict__ Whh,
                                  const float* __restrict__ bih, const float* __restrict__ bhh,
                                  const float* __restrict__ emb, const int* __restrict__ src,
                                  int t, bool enc)
{
    extern __shared__ float sm[];
    float* a_s  = sm + SA;          // [2][64*36]
    float* w_s  = sm + SWOFF;       // [32][516]
    int*  tok_s = (int*)(sm + STOK);

    if (cta >= 96) return;
    const bool isGi = (cta < 48);
    const int  j0   = (isGi ? cta : cta - 48) * GJT;
    const float* Wm   = isGi ? Wih : Whh;
    const float* bias = isGi ? bih : bhh;

    if (isGi && tid < B) {
        int tok;
        if (enc)          tok = src[tid*S + t];
        else if (t == 0)  tok = 0;  // SOS
        else {
            unsigned long long k = __ldcg(&g_key[tid]);
            tok = (int)(0xFFFFFFFFu - (unsigned)(k & 0xFFFFFFFFull));
        }
        tok_s[tid] = tok;
    }
    __syncthreads();   // tok visible before a-chunk issue

    // stage full W tile [32][512] -> [32][516]
    for (int idx = tid; idx < GJT*(H/4); idx += NTHR) {
        int r = idx >> 7, q = idx & 127;
        float4 v4 = *(const float4*)(Wm + (size_t)(j0 + r)*H + 4*q);
        *(float4*)(w_s + r*GWP + 4*q) = v4;
    }

    // a-chunk staging lambda: 64 rows x 8 float4 per chunk = 512 cp.async
    auto issueA = [&](int c, int p) {
        int r = tid >> 3, q = tid & 7;
        const float* srcp = isGi ? (emb + (size_t)tok_s[r]*H + c*KC + 4*q)
                                 : (g_h + r*H + c*KC + 4*q);
        cpasync16(a_s + p*ACH + r*PCH + 4*q, srcp);
        cp_commit();
    };

    const int tx = tid & 31, wy = tid >> 5;          // j = j0+tx, b = wy*4+jj
    float2 acc[4];
    #pragma unroll
    for (int j = 0; j < 4; j++) acc[j] = make_float2(0.f, 0.f);

    issueA(0, 0);
    for (int c = 0; c < H/KC; c++) {
        const int p = c & 1;
        if (c + 1 < H/KC) issueA(c + 1, p ^ 1);
        if (c + 1 < H/KC) cp_wait<1>(); else cp_wait<0>();
        __syncthreads();
        const float* ab = a_s + p*ACH + (wy*4)*PCH;
        const float* wr = w_s + tx*GWP + c*KC;
        #pragma unroll
        for (int q = 0; q < KC/4; q++) {
            float4 w4 = *(const float4*)(wr + 4*q);
            #pragma unroll
            for (int j = 0; j < 4; j++) {
                float4 a4 = *(const float4*)(ab + j*PCH + 4*q);
                acc[j] = ffma2(make_float2(a4.x, a4.y), make_float2(w4.x, w4.y), acc[j]);
                acc[j] = ffma2(make_float2(a4.z, a4.w), make_float2(w4.z, w4.w), acc[j]);
            }
        }
        __syncthreads();
    }

    const int j = j0 + tx;
    const float bv = bias[j];
    float* dst = isGi ? g_gi : g_gh;
    #pragma unroll
    for (int jj = 0; jj < 4; jj++)
        __stcg(dst + (size_t)(wy*4 + jj)*H3 + j, acc[jj].x + acc[jj].y + bv);
}

// ---------------- GRU combine + key reset ----------------
static __device__ void combine_pass(int cta, int tid)
{
    int g = cta*NTHR + tid;
    if (g < B) __stcg(&g_key[g], 0ull);
    if (g < B*H) {
        int b = g >> 9, i = g & (H-1);
        const float* gi = g_gi + (size_t)b*H3;
        const float* gh = g_gh + (size_t)b*H3;
        float ir = __ldcg(gi + i),       hr = __ldcg(gh + i);
        float iz = __ldcg(gi + H + i),   hz = __ldcg(gh + H + i);
        float in_= __ldcg(gi + 2*H + i), hn = __ldcg(gh + 2*H + i);
        float r = 1.f / (1.f + expf(-(ir + hr)));
        float z = 1.f / (1.f + expf(-(iz + hz)));
        float n = tanhf(in_ + r*hn);
        float h = __ldcg(g_h + g);
        __stcg(g_h + g, (1.f - z)*n + z*h);
    }
}

// ---------------- FC + argmax: pred = h@fcW^T + fcb ----------------
static __device__ void fc_pass(int cta, int tid,
                               const float* __restrict__ fcW, const float* __restrict__ fcb,
                               float* __restrict__ out, int t, int T)
{
    extern __shared__ float sm[];
    float* h_s = sm + SA;          // [2][64*36]
    float* w_s = sm + SWOFF;       // [2][224*36]
    const int v0 = cta * FVT;
    if (v0 >= V) return;

    auto issue = [&](int c, int p) {
        // h chunk: 64 rows x 8 float4 = 512
        {
            int r = tid >> 3, q = tid & 7;
            cpasync16(h_s + p*ACH + r*PCH + 4*q, g_h + r*H + c*KC + 4*q);
        }
        // w chunk: 224 rows x 8 float4 = 1792
        for (int idx = tid; idx < FVT*(KC/4); idx += NTHR) {
            int r = idx >> 3, q = idx & 7;
            int v = v0 + r; if (v >= V) v = V - 1;
            cpasync16(w_s + p*WCH + r*PCH + 4*q, fcW + (size_t)v*H + c*KC + 4*q);
        }
        cp_commit();
    };

    const int tx = tid & 31, wy = tid >> 5;   // v = v0+tx+32i (i<7), b = wy*4+j (j<4)
    float2 acc[7][4];
    #pragma unroll
    for (int i = 0; i < 7; i++)
        #pragma unroll
        for (int j = 0; j < 4; j++) acc[i][j] = make_float2(0.f, 0.f);

    issue(0, 0);
    for (int c = 0; c < H/KC; c++) {
        const int p = c & 1;
        if (c + 1 < H/KC) issue(c + 1, p ^ 1);
        if (c + 1 < H/KC) cp_wait<1>(); else cp_wait<0>();
        __syncthreads();
        const float* hb = h_s + p*ACH + (wy*4)*PCH;
        const float* wb = w_s + p*WCH + tx*PCH;
        #pragma unroll
        for (int q = 0; q < KC/4; q++) {
            float4 h4[4];
            #pragma unroll
            for (int j = 0; j < 4; j++) h4[j] = *(const float4*)(hb + j*PCH + 4*q);
            #pragma unroll
            for (int i = 0; i < 7; i++) {
                float4 w4 = *(const float4*)(wb + i*32*PCH + 4*q);
                #pragma unroll
                for (int j = 0; j < 4; j++) {
                    acc[i][j] = ffma2(make_float2(h4[j].x, h4[j].y),
                                      make_float2(w4.x, w4.y), acc[i][j]);
                    acc[i][j] = ffma2(make_float2(h4[j].z, h4[j].w),
                                      make_float2(w4.z, w4.w), acc[i][j]);
                }
            }
        }
        __syncthreads();
    }

    unsigned long long bestKey[4];
    #pragma unroll
    for (int j = 0; j < 4; j++) bestKey[j] = 0ull;

    #pragma unroll
    for (int i = 0; i < 7; i++) {
        int v = v0 + tx + 32*i;
        if (v < V) {
            float bv = fcb[v];
            #pragma unroll
            for (int j = 0; j < 4; j++) {
                float p = acc[i][j].x + acc[i][j].y + bv;
                int b = wy*4 + j;
                out[((size_t)b*T + t)*V + v] = p;
                unsigned long long key = makeKey(p, v);
                if (key > bestKey[j]) bestKey[j] = key;
            }
        }
    }
    #pragma unroll
    for (int j = 0; j < 4; j++) {
        unsigned long long k = bestKey[j];
        #pragma unroll
        for (int off = 16; off > 0; off >>= 1) {
            unsigned long long o = __shfl_down_sync(0xFFFFFFFFu, k, off);
            if (o > k) k = o;
        }
        if (tx == 0) atomicMax(&g_key[wy*4 + j], k);
    }
}

// ---------------- kernels ----------------
__global__ void init_kernel()
{
    int g = blockIdx.x * blockDim.x + threadIdx.x;
    if (g < B*H) g_h[g] = 0.f;
    if (g < B)   g_key[g] = 0ull;
    if (g == 0)  g_count = 0u;
}

__global__ void __launch_bounds__(NTHR, 1) seq2seq_kernel(
    const int* __restrict__ src, const float* __restrict__ emb,
    const float* __restrict__ eWih, const float* __restrict__ eWhh,
    const float* __restrict__ ebih, const float* __restrict__ ebhh,
    const float* __restrict__ dWih, const float* __restrict__ dWhh,
    const float* __restrict__ dbih, const float* __restrict__ dbhh,
    const float* __restrict__ fcW,  const float* __restrict__ fcb,
    float* __restrict__ out, int T)
{
    const int cta = blockIdx.x, tid = threadIdx.x;
    unsigned gen = 0;

    // ---- encoder ----
    for (int t = 0; t < S; t++) {
        gates_pass(cta, tid, eWih, eWhh, ebih, ebhh, emb, src, t, true);
        gsync(++gen * NCTA);
        combine_pass(cta, tid);
        gsync(++gen * NCTA);
    }
    // ---- decoder ----
    for (int t = 0; t < T; t++) {
        gates_pass(cta, tid, dWih, dWhh, dbih, dbhh, emb, src, t, false);
        gsync(++gen * NCTA);
        combine_pass(cta, tid);
        gsync(++gen * NCTA);
        fc_pass(cta, tid, fcW, fcb, out, t, T);
        gsync(++gen * NCTA);
    }
}

extern "C" void kernel_launch(void* const* d_in, const int* in_sizes, int n_in,
                              void* d_out, int out_size)
{
    const int*   src  = (const int*)  d_in[0];
    const float* emb  = (const float*)d_in[1];
    const float* eWih = (const float*)d_in[2];
    const float* eWhh = (const float*)d_in[3];
    const float* ebih = (const float*)d_in[4];
    const float* ebhh = (const float*)d_in[5];
    const float* dWih = (const float*)d_in[6];
    const float* dWhh = (const float*)d_in[7];
    const float* dbih = (const float*)d_in[8];
    const float* dbhh = (const float*)d_in[9];
    const float* fcW  = (const float*)d_in[10];
    const float* fcb  = (const float*)d_in[11];
    float* out = (float*)d_out;
    const int T = out_size / (B * V);   // 80

    cudaFuncSetAttribute(seq2seq_kernel,
                         cudaFuncAttributeMaxDynamicSharedMemorySize, SMEM_BYTES);

    init_kernel<<<64, 512>>>();
    seq2seq_kernel<<<NCTA, NTHR, SMEM_BYTES>>>(
        src, emb, eWih, eWhh, ebih, ebhh,
        dWih, dWhh, dbih, dbhh, fcW, fcb, out, T);
}